// round 17
// baseline (speedup 1.0000x reference)
#include <cuda_runtime.h>
#include <cuda_bf16.h>
#include <math.h>

// Problem constants
#define BATCH 2
#define SEQ   1024
#define HID   2048
#define NH    32
#define NKV   4
#define GRP   8
#define HD    128
#define NQKV  5120
#define TOK   (BATCH*SEQ)
#define SCALE 0.08838834764831845f
#define QSCALE (0.08838834764831845f * 1.4426950408889634f)
#define RMS_EPS 1e-6f

// -------------------- scratch -------------------------------------------
__device__ float    g_qkv[TOK * NQKV];
__device__ unsigned g_ht[TOK * HID];                // hidden as tf32
__device__ unsigned g_qt[BATCH * NH * SEQ * HD];    // tf32, pre-scaled by QSCALE
__device__ unsigned g_kt[BATCH * NKV * SEQ * HD];   // tf32
__device__ unsigned g_vtT[BATCH * NKV * HD * SEQ];  // tf32, transposed [b][kh][d][s]
__device__ unsigned g_ctx[TOK * NH * HD];           // ctx as tf32
__device__ unsigned g_wqkv_t[NQKV * HID];
__device__ unsigned g_wo_t[HID * (NH * HD)];

__device__ __forceinline__ unsigned f2tf32(float x) {
    unsigned y;
    asm("cvt.rna.tf32.f32 %0, %1;" : "=r"(y) : "f"(x));
    return y;
}

__device__ __forceinline__ float ex2f(float x) {
    float y;
    asm("ex2.approx.f32 %0, %1;" : "=f"(y) : "f"(x));
    return y;
}

__device__ __forceinline__ void mma_tf32(float c[4],
    unsigned a0, unsigned a1, unsigned a2, unsigned a3,
    unsigned b0, unsigned b1)
{
    asm volatile(
        "mma.sync.aligned.m16n8k8.row.col.f32.tf32.tf32.f32 "
        "{%0,%1,%2,%3}, {%4,%5,%6,%7}, {%8,%9}, {%0,%1,%2,%3};"
        : "+f"(c[0]), "+f"(c[1]), "+f"(c[2]), "+f"(c[3])
        : "r"(a0), "r"(a1), "r"(a2), "r"(a3), "r"(b0), "r"(b1));
}

__device__ __forceinline__ void ldsm_x4(unsigned r[4], unsigned addr) {
    asm volatile("ldmatrix.sync.aligned.m8n8.x4.shared.b16 {%0,%1,%2,%3}, [%4];"
                 : "=r"(r[0]), "=r"(r[1]), "=r"(r[2]), "=r"(r[3]) : "r"(addr));
}

#define CP_ASYNC16(dst_u32, src_ptr) \
    asm volatile("cp.async.cg.shared.global [%0], [%1], 16;" :: "r"(dst_u32), "l"(src_ptr))
#define CP_COMMIT() asm volatile("cp.async.commit_group;")
#define CP_WAIT0()  asm volatile("cp.async.wait_group 0;")
#define CP_WAIT1()  asm volatile("cp.async.wait_group 1;")

// ---------------------------------------------------------------------------
// Elementwise tf32 convert (for hidden states)
// ---------------------------------------------------------------------------
__global__ __launch_bounds__(256) void cvt_tf32(
    const float* __restrict__ in, unsigned* __restrict__ out)
{
    const int i = (blockIdx.x * 256 + threadIdx.x) * 4;
    const float4 v = *(const float4*)(in + i);
    uint4 o = make_uint4(f2tf32(v.x), f2tf32(v.y), f2tf32(v.z), f2tf32(v.w));
    *(uint4*)(out + i) = o;
}

// ---------------------------------------------------------------------------
// Transpose + tf32-convert (weights; unchanged)
// ---------------------------------------------------------------------------
__global__ __launch_bounds__(256) void transpose_tf32(
    const float* __restrict__ in, unsigned* __restrict__ out, int K, int N)
{
    __shared__ unsigned t[32][33];
    const int tx = threadIdx.x, ty = threadIdx.y;
    const int n0 = blockIdx.x * 32, k0 = blockIdx.y * 32;
#pragma unroll
    for (int i = 0; i < 4; i++) {
        const int k = k0 + ty + i * 8;
        t[ty + i * 8][tx] = f2tf32(in[(size_t)k * N + n0 + tx]);
    }
    __syncthreads();
#pragma unroll
    for (int i = 0; i < 4; i++) {
        const int n = n0 + ty + i * 8;
        out[(size_t)n * K + k0 + tx] = t[tx][ty + i * 8];
    }
}

// ---------------------------------------------------------------------------
// TT tf32 GEMM v2: C[M,N] = A[M,K] @ Bt[N,K]^T, both operands tf32 u32.
// CTA tile 256x128, 8 warps of 64x64 (4.0 mma/ldsm, 4x A-frag reuse).
// 3-stage cp.async, one barrier per k-iter (trailing sync removed: stage
// (it+2)%3 was last read in iter it-1, completed before this iter's sync).
// ---------------------------------------------------------------------------
#define GS 36
#define GAW (256 * GS)            // A words per stage
#define GBW (128 * GS)            // B words per stage
#define GSW (GAW + GBW)           // words per stage
#define GNST 3

__global__ __launch_bounds__(256, 1) void gemm_tt2(
    const unsigned* __restrict__ At, const unsigned* __restrict__ Bt,
    float* __restrict__ C, int M, int N, int K)
{
    extern __shared__ unsigned sh[];   // [GNST][GSW]

    const int tid  = threadIdx.x;
    const int lane = tid & 31;
    const int wid  = tid >> 5;
    const int bm = blockIdx.y, bn = blockIdx.x;

    const int wm = (wid & 3) * 64;    // 4 m-bands of 64
    const int wn = (wid >> 2) * 64;   // 2 n-bands of 64
    const int qr = lane >> 2, ql = lane & 3;

    const unsigned s_base = (unsigned)__cvta_generic_to_shared(sh);

    const unsigned* Ag = At + (size_t)(bm * 256) * K;
    const unsigned* Bg = Bt + (size_t)(bn * 128) * K;

    // staging: A 2048 16B-chunks (256x8), B 1024 (128x8)
    auto issue_stage = [&](int it) {
        const int st = it % GNST;
        const int k0 = it << 5;
        const unsigned sb = s_base + st * (GSW * 4);
#pragma unroll
        for (int u = 0; u < 8; u++) {
            const int i = tid + u * 256;
            const int r = i >> 3, ch = i & 7;
            CP_ASYNC16(sb + (r * GS + ch * 4) * 4, Ag + (size_t)r * K + k0 + ch * 4);
        }
#pragma unroll
        for (int u = 0; u < 4; u++) {
            const int i = tid + u * 256;
            const int r = i >> 3, ch = i & 7;
            CP_ASYNC16(sb + GAW * 4 + (r * GS + ch * 4) * 4,
                       Bg + (size_t)r * K + k0 + ch * 4);
        }
        CP_COMMIT();
    };

    // fragment byte offsets (within a stage)
    unsigned a_off[4];
#pragma unroll
    for (int i = 0; i < 4; i++)
        a_off[i] = ((wm + i * 16 + (lane & 7) + (lane & 8)) * GS +
                    ((lane >> 4) << 2)) * 4;
    unsigned b_off[4];
#pragma unroll
    for (int jp = 0; jp < 4; jp++)
        b_off[jp] = GAW * 4 +
                    ((wn + jp * 16 + (lane & 7) + ((lane & 16) >> 1)) * GS +
                     (((lane >> 3) & 1) << 2)) * 4;

    float acc[4][8][4];
#pragma unroll
    for (int i = 0; i < 4; i++)
#pragma unroll
        for (int j = 0; j < 8; j++)
#pragma unroll
            for (int c = 0; c < 4; c++) acc[i][j][c] = 0.f;

    const int niter = K >> 5;
    issue_stage(0);
    if (niter > 1) issue_stage(1);

    for (int it = 0; it < niter; ++it) {
        if (it + 1 < niter) { CP_WAIT1(); } else { CP_WAIT0(); }
        __syncthreads();
        if (it + 2 < niter) issue_stage(it + 2);

        const unsigned sb = s_base + (it % GNST) * (GSW * 4);
#pragma unroll
        for (int kk = 0; kk < 4; kk++) {
            const unsigned koff = kk * 32;
            unsigned a[4][4];
#pragma unroll
            for (int i = 0; i < 4; i++)
                ldsm_x4(a[i], sb + a_off[i] + koff);
#pragma unroll
            for (int jp = 0; jp < 4; jp++) {
                unsigned bfr[4];
                ldsm_x4(bfr, sb + b_off[jp] + koff);
#pragma unroll
                for (int i = 0; i < 4; i++) {
                    mma_tf32(acc[i][2 * jp],     a[i][0], a[i][1], a[i][2], a[i][3], bfr[0], bfr[1]);
                    mma_tf32(acc[i][2 * jp + 1], a[i][0], a[i][1], a[i][2], a[i][3], bfr[2], bfr[3]);
                }
            }
        }
    }

#pragma unroll
    for (int i = 0; i < 4; i++) {
        const int r0 = bm * 256 + wm + i * 16 + qr;
#pragma unroll
        for (int j = 0; j < 8; j++) {
            const int c = bn * 128 + wn + j * 8 + ql * 2;
            *(float2*)(C + (size_t)r0 * N + c)       = make_float2(acc[i][j][0], acc[i][j][1]);
            *(float2*)(C + (size_t)(r0 + 8) * N + c) = make_float2(acc[i][j][2], acc[i][j][3]);
        }
    }
}

// ---------------------------------------------------------------------------
// RMSNorm + RoPE + split — emits tf32; Q pre-scaled; V transposed (unchanged)
// ---------------------------------------------------------------------------
__global__ __launch_bounds__(128) void norm_rope_kernel(
    const float* __restrict__ qkv, const float* __restrict__ cosb,
    const float* __restrict__ sinb, const float* __restrict__ qw,
    const float* __restrict__ kw,
    unsigned* __restrict__ Q, unsigned* __restrict__ K, unsigned* __restrict__ Vt)
{
    const int token = blockIdx.x;
    const int slot  = blockIdx.y;
    const int d     = threadIdx.x;
    const int b = token / SEQ, s = token % SEQ;

    const float x = qkv[(size_t)token * NQKV + slot * HD + d];

    if (slot >= 36) {
        const int kh = slot - 36;
        Vt[(((size_t)(b * NKV + kh) * HD) + d) * SEQ + s] = f2tf32(x);
        return;
    }

    __shared__ float xn[HD];
    __shared__ float red[4];

    float ss = x * x;
#pragma unroll
    for (int o = 16; o > 0; o >>= 1) ss += __shfl_xor_sync(0xffffffffu, ss, o);
    if ((d & 31) == 0) red[d >> 5] = ss;
    __syncthreads();
    const float tot = red[0] + red[1] + red[2] + red[3];
    const float inv = rsqrtf(tot * (1.0f / HD) + RMS_EPS);

    const float* w = (slot < 32) ? qw : kw;
    const float v = x * inv * w[d];
    xn[d] = v;
    __syncthreads();

    const float rot = (d < 64) ? -xn[d + 64] : xn[d - 64];
    const float c  = cosb[(size_t)s * HD + d];
    const float sn = sinb[(size_t)s * HD + d];
    const float out = v * c + rot * sn;

    if (slot < 32)
        Q[((size_t)(b * NH + slot) * SEQ + s) * HD + d] = f2tf32(out * QSCALE);
    else
        K[((size_t)(b * NKV + (slot - 32)) * SEQ + s) * HD + d] = f2tf32(out);
}

// ---------------------------------------------------------------------------
// Tensor-core causal GQA flash attention v6 (unchanged from R15 @770us)
// ---------------------------------------------------------------------------
#define CHQ   (128 * 36)
#define KCH   (32 * 36)
#define KSTG  (4 * KCH)
#define VSTG  (128 * 36)
#define QW    (4 * CHQ)
#define NSTG  3

__global__ __launch_bounds__(512) void attn_tc6(
    const unsigned* __restrict__ Qt, const unsigned* __restrict__ Kt,
    const unsigned* __restrict__ VtT)
{
    extern __shared__ unsigned ash[];
    unsigned* Qs = ash;
    unsigned* Ks = Qs + QW;
    unsigned* Vs = Ks + NSTG * KSTG;
    unsigned* Ps = Vs + NSTG * VSTG;
    float*   l_s = (float*)(Ps + CHQ);
    float*   lp  = l_s + 128;

    const int mt = 31 - blockIdx.x;
    const int hg = blockIdx.y;
    const int b  = blockIdx.z;
    const int kh = hg >> 1;
    const int hbase = kh * GRP + (hg & 1) * 4;
    const int m0 = mt * 32;

    const int tid = threadIdx.x, lane = tid & 31, wid = tid >> 5;
    const int qr = lane >> 2, ql = lane & 3;
    const int wm  = (wid & 7) * 16;
    const int wn  = (wid >> 3) * 16;
    const int wn3 = (wid >> 3) * 64;
    const int nb  = wid >> 3;

    const unsigned* Kb = Kt  + ((size_t)(b * NKV + kh) * SEQ) * HD;
    const unsigned* Vb = VtT + ((size_t)(b * NKV + kh) * HD) * SEQ;

    const unsigned smem_b = (unsigned)__cvta_generic_to_shared(ash);
    const unsigned qs_base = smem_b;
    const unsigned ks_b    = smem_b + QW * 4;
    const unsigned vs_b    = ks_b + NSTG * KSTG * 4;
    const unsigned ps_base = vs_b + NSTG * VSTG * 4;

    const int ntiles = mt + 1;

    auto issue_kv = [&](int t) {
        const int st = t % NSTG;
        const int n0 = t * 32;
#pragma unroll
        for (int u = 0; u < 2; u++) {
            const int i = tid + u * 512;
            const int r = i >> 5, cgrp = i & 31;
            const unsigned kdst = ks_b + (st * KSTG + (cgrp >> 3) * KCH +
                                          r * 36 + (cgrp & 7) * 4) * 4;
            CP_ASYNC16(kdst, Kb + (size_t)(n0 + r) * HD + cgrp * 4);
            const int dv = i >> 3, ch = i & 7;
            const unsigned vdst = vs_b + (st * VSTG + dv * 36 + ch * 4) * 4;
            CP_ASYNC16(vdst, Vb + (size_t)dv * SEQ + n0 + ch * 4);
        }
        CP_COMMIT();
    };

    issue_kv(0);
    if (ntiles > 1) issue_kv(1);

    for (int i = tid; i < 128 * 32; i += 512) {
        const int r = i >> 5, cw = (i & 31) * 4;
        const int hl = r >> 5, pos = r & 31;
        const uint4 q4 = *(const uint4*)(Qt +
            ((size_t)(b * NH + hbase + hl) * SEQ + m0 + pos) * HD + cw);
        *(uint4*)&Qs[(cw >> 5) * CHQ + r * 36 + (cw & 31)] = q4;
    }
    if (tid < 128) l_s[tid] = 0.f;

    const unsigned a_off = ((wm + (lane & 7) + (lane & 8)) * 36 +
                            ((lane >> 4) << 2)) * 4;
    const unsigned bk_off = ((wn + (lane & 7) + ((lane & 16) >> 1)) * 36 +
                             (((lane >> 3) & 1) << 2)) * 4;
    unsigned vb_off[4];
#pragma unroll
    for (int jp = 0; jp < 4; jp++)
        vb_off[jp] = ((wn3 + jp * 16 + (lane & 7) + ((lane & 16) >> 1)) * 36 +
                      (((lane >> 3) & 1) << 2)) * 4;

    const int row0 = wm + qr, row1 = row0 + 8;
    const int p0pos = row0 & 31, p1pos = row1 & 31;

    float oacc[8][4];
#pragma unroll
    for (int j = 0; j < 8; j++)
#pragma unroll
        for (int c = 0; c < 4; c++) oacc[j][c] = 0.f;

    for (int t = 0; t < ntiles; ++t) {
        const int st = t % NSTG;
        if (t + 1 < ntiles) { CP_WAIT1(); } else { CP_WAIT0(); }
        __syncthreads();

        if (t + 2 < ntiles) issue_kv(t + 2);

        float sacc[2][4];
#pragma unroll
        for (int j = 0; j < 2; j++)
#pragma unroll
            for (int c = 0; c < 4; c++) sacc[j][c] = 0.f;

        const unsigned k_stage = ks_b + st * (KSTG * 4);
        unsigned afr[2][4], bfr[2][4];
        ldsm_x4(afr[0], qs_base + a_off);
        ldsm_x4(bfr[0], k_stage + bk_off);
#pragma unroll
        for (int k8 = 0; k8 < 16; k8++) {
            const int cur = k8 & 1;
            if (k8 + 1 < 16) {
                const int kn = k8 + 1;
                ldsm_x4(afr[cur ^ 1], qs_base + (kn >> 2) * (CHQ * 4) + a_off + (kn & 3) * 32);
                ldsm_x4(bfr[cur ^ 1], k_stage + (kn >> 2) * (KCH * 4) + bk_off + (kn & 3) * 32);
            }
            mma_tf32(sacc[0], afr[cur][0], afr[cur][1], afr[cur][2], afr[cur][3],
                     bfr[cur][0], bfr[cur][1]);
            mma_tf32(sacc[1], afr[cur][0], afr[cur][1], afr[cur][2], afr[cur][3],
                     bfr[cur][2], bfr[cur][3]);
        }

        const bool diag = (t == ntiles - 1);
        float ls0 = 0.f, ls1 = 0.f;
#pragma unroll
        for (int j = 0; j < 2; j++) {
            const int cg = wn + j * 8 + 2 * ql;
            float p00 = ex2f(sacc[j][0]);
            float p01 = ex2f(sacc[j][1]);
            float p10 = ex2f(sacc[j][2]);
            float p11 = ex2f(sacc[j][3]);
            if (diag) {
                if (cg     > p0pos) p00 = 0.f;
                if (cg + 1 > p0pos) p01 = 0.f;
                if (cg     > p1pos) p10 = 0.f;
                if (cg + 1 > p1pos) p11 = 0.f;
            }
            ls0 += p00 + p01;
            ls1 += p10 + p11;
            Ps[row0 * 36 + cg]     = f2tf32(p00);
            Ps[row0 * 36 + cg + 1] = f2tf32(p01);
            Ps[row1 * 36 + cg]     = f2tf32(p10);
            Ps[row1 * 36 + cg + 1] = f2tf32(p11);
        }
        ls0 += __shfl_xor_sync(0xffffffffu, ls0, 1);
        ls0 += __shfl_xor_sync(0xffffffffu, ls0, 2);
        ls1 += __shfl_xor_sync(0xffffffffu, ls1, 1);
        ls1 += __shfl_xor_sync(0xffffffffu, ls1, 2);
        if (ql == 0) {
            lp[nb * 128 + row0] = ls0;
            lp[nb * 128 + row1] = ls1;
        }
        __syncthreads();

        if (tid < 128) l_s[tid] += lp[tid] + lp[128 + tid];

        const unsigned v_stage = vs_b + st * (VSTG * 4);
#pragma unroll
        for (int kk = 0; kk < 4; kk++) {
            const unsigned koff = kk * 32;
            unsigned pafr[4];
            ldsm_x4(pafr, ps_base + a_off + koff);
            unsigned bv0[4], bv1[4], bv2[4], bv3[4];
            ldsm_x4(bv0, v_stage + vb_off[0] + koff);
            ldsm_x4(bv1, v_stage + vb_off[1] + koff);
            ldsm_x4(bv2, v_stage + vb_off[2] + koff);
            ldsm_x4(bv3, v_stage + vb_off[3] + koff);
            mma_tf32(oacc[0], pafr[0], pafr[1], pafr[2], pafr[3], bv0[0], bv0[1]);
            mma_tf32(oacc[1], pafr[0], pafr[1], pafr[2], pafr[3], bv0[2], bv0[3]);
            mma_tf32(oacc[2], pafr[0], pafr[1], pafr[2], pafr[3], bv1[0], bv1[1]);
            mma_tf32(oacc[3], pafr[0], pafr[1], pafr[2], pafr[3], bv1[2], bv1[3]);
            mma_tf32(oacc[4], pafr[0], pafr[1], pafr[2], pafr[3], bv2[0], bv2[1]);
            mma_tf32(oacc[5], pafr[0], pafr[1], pafr[2], pafr[3], bv2[2], bv2[3]);
            mma_tf32(oacc[6], pafr[0], pafr[1], pafr[2], pafr[3], bv3[0], bv3[1]);
            mma_tf32(oacc[7], pafr[0], pafr[1], pafr[2], pafr[3], bv3[2], bv3[3]);
        }
    }

    __syncthreads();

    const float il0 = 1.0f / l_s[row0];
    const float il1 = 1.0f / l_s[row1];
    const int h = hbase + (row0 >> 5);
    const int pos0 = m0 + p0pos, pos1 = m0 + p1pos;
#pragma unroll
    for (int j = 0; j < 8; j++) {
        const int col = wn3 + j * 8 + 2 * ql;
        unsigned* o0 = g_ctx + ((size_t)b * SEQ + pos0) * (NH * HD) + h * HD + col;
        unsigned* o1 = g_ctx + ((size_t)b * SEQ + pos1) * (NH * HD) + h * HD + col;
        *(uint2*)o0 = make_uint2(f2tf32(oacc[j][0] * il0), f2tf32(oacc[j][1] * il0));
        *(uint2*)o1 = make_uint2(f2tf32(oacc[j][2] * il1), f2tf32(oacc[j][3] * il1));
    }
}

// ---------------------------------------------------------------------------
extern "C" void kernel_launch(void* const* d_in, const int* in_sizes, int n_in,
                              void* d_out, int out_size)
{
    const float* hidden = (const float*)d_in[0];
    const float* cosb   = (const float*)d_in[1];
    const float* sinb   = (const float*)d_in[2];
    const float* w_qkv  = (const float*)d_in[3];
    const float* q_w    = (const float*)d_in[4];
    const float* k_w    = (const float*)d_in[5];
    const float* w_o    = (const float*)d_in[6];
    float* out = (float*)d_out;

    float *qkv_p;
    unsigned *ht_p, *qt_p, *kt_p, *vt_p, *ctx_p, *wqkvt_p, *wot_p;
    cudaGetSymbolAddress((void**)&qkv_p,   g_qkv);
    cudaGetSymbolAddress((void**)&ht_p,    g_ht);
    cudaGetSymbolAddress((void**)&qt_p,    g_qt);
    cudaGetSymbolAddress((void**)&kt_p,    g_kt);
    cudaGetSymbolAddress((void**)&vt_p,    g_vtT);
    cudaGetSymbolAddress((void**)&ctx_p,   g_ctx);
    cudaGetSymbolAddress((void**)&wqkvt_p, g_wqkv_t);
    cudaGetSymbolAddress((void**)&wot_p,   g_wo_t);

    const int gemm_smem = GNST * GSW * 4;   // 165888 bytes
    cudaFuncSetAttribute(gemm_tt2, cudaFuncAttributeMaxDynamicSharedMemorySize, gemm_smem);
    const int attn_smem = (QW + NSTG * KSTG + NSTG * VSTG + CHQ + 128 + 256) * 4;
    cudaFuncSetAttribute(attn_tc6, cudaFuncAttributeMaxDynamicSharedMemorySize, attn_smem);

    // 0) pre-convert: weights (transposed) + hidden (elementwise)
    transpose_tf32<<<dim3(NQKV / 32, HID / 32), dim3(32, 8)>>>(w_qkv, wqkvt_p, HID, NQKV);
    transpose_tf32<<<dim3(HID / 32, (NH * HD) / 32), dim3(32, 8)>>>(w_o, wot_p, NH * HD, HID);
    cvt_tf32<<<(TOK * HID) / 1024, 256>>>(hidden, ht_p);

    // 1) QKV projection: 256x128 tiles -> grid (40, 8)
    gemm_tt2<<<dim3(NQKV / 128, TOK / 256), 256, gemm_smem>>>(ht_p, wqkvt_p, qkv_p, TOK, NQKV, HID);

    // 2) RMSNorm + RoPE + split
    norm_rope_kernel<<<dim3(TOK, 40), 128>>>(qkv_p, cosb, sinb, q_w, k_w, qt_p, kt_p, vt_p);

    // 3) causal GQA attention
    attn_tc6<<<dim3(32, 8, BATCH), 512, attn_smem>>>(qt_p, kt_p, vt_p);

    // 4) output projection: grid (16, 8) = 128 blocks = one full wave
    gemm_tt2<<<dim3(HID / 128, TOK / 256), 256, gemm_smem>>>(ctx_p, wot_p, out, TOK, HID, NH * HD);

    (void)in_sizes; (void)n_in; (void)out_size;
}